// round 8
// baseline (speedup 1.0000x reference)
#include <cuda_runtime.h>
#include <cuda_bf16.h>
#include <cstdint>

// Swin layer: split-bf16 HMMA QKV GEMM + fused flash-attention + O-proj.
#define NTOK 131072          // 32 * 64 * 64 tokens

// -------- device scratch (allocation-free rule) --------
__device__ __nv_bfloat16 g_qkvh[(size_t)NTOK * 768];
__device__ __nv_bfloat16 g_qkvl[(size_t)NTOK * 768];
__device__ __nv_bfloat16 g_yh[NTOK * 256];      // pass-1 output, image layout
__device__ __nv_bfloat16 g_yl[NTOK * 256];
__device__ __nv_bfloat16 g_wtq_hi[768 * 256];   // W_qkv^T  [N][K]
__device__ __nv_bfloat16 g_wtq_lo[768 * 256];
__device__ __nv_bfloat16 g_wto_hi[256 * 256];   // W_o^T    [N][K]
__device__ __nv_bfloat16 g_wto_lo[256 * 256];

// ======================= helpers =======================
__device__ __forceinline__ uint32_t smem_u32(const void* p) {
    uint32_t a;
    asm("{ .reg .u64 t; cvta.to.shared.u64 t, %1; cvt.u32.u64 %0, t; }" : "=r"(a) : "l"(p));
    return a;
}
__device__ __forceinline__ void ldsm4(uint32_t r[4], uint32_t addr) {
    asm volatile("ldmatrix.sync.aligned.m8n8.x4.shared.b16 {%0,%1,%2,%3}, [%4];"
                 : "=r"(r[0]), "=r"(r[1]), "=r"(r[2]), "=r"(r[3]) : "r"(addr));
}
__device__ __forceinline__ void ldsm4t(uint32_t r[4], uint32_t addr) {
    asm volatile("ldmatrix.sync.aligned.m8n8.x4.trans.shared.b16 {%0,%1,%2,%3}, [%4];"
                 : "=r"(r[0]), "=r"(r[1]), "=r"(r[2]), "=r"(r[3]) : "r"(addr));
}
__device__ __forceinline__ void mma16816(float d[4], const uint32_t a[4],
                                         uint32_t b0, uint32_t b1) {
    asm volatile(
        "mma.sync.aligned.m16n8k16.row.col.f32.bf16.bf16.f32 "
        "{%0,%1,%2,%3}, {%4,%5,%6,%7}, {%8,%9}, {%0,%1,%2,%3};"
        : "+f"(d[0]), "+f"(d[1]), "+f"(d[2]), "+f"(d[3])
        : "r"(a[0]), "r"(a[1]), "r"(a[2]), "r"(a[3]), "r"(b0), "r"(b1));
}
__device__ __forceinline__ uint32_t pk(float c0, float c1) {   // bf16x2(lo=c0, hi=c1)
    uint32_t d;
    asm("cvt.rn.bf16x2.f32 %0, %1, %2;" : "=r"(d) : "f"(c1), "f"(c0));
    return d;
}
__device__ __forceinline__ float bf16rt(float v) {
    return __bfloat162float(__float2bfloat16(v));
}
__device__ __forceinline__ int regid(int wh, int ww, int t) {
    int r = t >> 3, c = t & 7;
    int hr = (wh == 7) ? ((r < 4) ? 1 : 2) : 0;
    int wr = (ww == 7) ? ((c < 4) ? 1 : 2) : 0;
    return hr * 3 + wr;
}

// ======================= prep: W^T hi/lo split =======================
__global__ void prep_kernel(const float* __restrict__ wqkv, const float* __restrict__ wo) {
    int i = blockIdx.x * blockDim.x + threadIdx.x;
    if (i < 768 * 256) {
        int n = i >> 8, k = i & 255;
        float f = wqkv[k * 768 + n];
        float h = bf16rt(f);
        g_wtq_hi[i] = __float2bfloat16(h);
        g_wtq_lo[i] = __float2bfloat16(f - h);
    } else if (i < 768 * 256 + 256 * 256) {
        int j = i - 768 * 256;
        int n = j >> 8, k = j & 255;
        float f = wo[k * 256 + n];
        float h = bf16rt(f);
        g_wto_hi[j] = __float2bfloat16(h);
        g_wto_lo[j] = __float2bfloat16(f - h);
    }
}

// ======================= QKV GEMM kernel =======================
// qkv[tok, 0:768] = A[tok, 0:256] @ Wqkv + b  -> split bf16 out.
// pass 0: A = gather(x fp32, +0 roll); pass 1: A = gather(g_y bf16 split, +4 roll)
#define LDA      264
#define A_LO_OFF 67584
#define GB_OFF   135168
#define B_BUF    36864
#define B_HALF   18432
#define LDB_B    144
#define GS_SMEM  (GB_OFF + 2 * B_BUF)

__global__ __launch_bounds__(256, 1)
void gemm_qkv(const float* __restrict__ xin,
              const __nv_bfloat16* __restrict__ yh_in, const __nv_bfloat16* __restrict__ yl_in,
              const __nv_bfloat16* __restrict__ wh, const __nv_bfloat16* __restrict__ wl,
              const float* __restrict__ bias,
              __nv_bfloat16* __restrict__ qh_out, __nv_bfloat16* __restrict__ ql_out,
              int shifted)
{
    extern __shared__ char sb[];
    const uint32_t smb = smem_u32(sb);
    const int tid = threadIdx.x, wid = tid >> 5, lane = tid & 31;
    const int blk = blockIdx.x;
    const int sh = shifted ? 4 : 0;

    // ---- load A (128 rows x 256), window-gather with roll ----
    for (int g = tid; g < 4096; g += 256) {
        int t = g >> 5;
        int col0 = (g & 31) * 8;
        int tok = blk * 128 + t;
        int m = tok >> 12, w = (tok >> 6) & 63, tt = tok & 63;
        int gh = ((w >> 3) * 8 + (tt >> 3) + sh) & 63;
        int gw = ((w & 7) * 8 + (tt & 7) + sh) & 63;
        size_t idx = (size_t)((m * 64 + gh) * 64 + gw) * 256 + col0;
        uint32_t off = ((uint32_t)t * LDA + col0) * 2;
        if (!shifted) {
            const float* sp = xin + idx;
            float4 f0 = *(const float4*)sp, f1 = *(const float4*)(sp + 4);
            float fv[8] = {f0.x, f0.y, f0.z, f0.w, f1.x, f1.y, f1.z, f1.w};
            uint32_t hw[4], lw[4];
#pragma unroll
            for (int q = 0; q < 4; ++q) {
                float h0 = bf16rt(fv[2 * q]), h1 = bf16rt(fv[2 * q + 1]);
                hw[q] = pk(h0, h1);
                lw[q] = pk(fv[2 * q] - h0, fv[2 * q + 1] - h1);
            }
            *(uint4*)(sb + off)            = make_uint4(hw[0], hw[1], hw[2], hw[3]);
            *(uint4*)(sb + A_LO_OFF + off) = make_uint4(lw[0], lw[1], lw[2], lw[3]);
        } else {
            *(uint4*)(sb + off)            = *(const uint4*)(yh_in + idx);
            *(uint4*)(sb + A_LO_OFF + off) = *(const uint4*)(yl_in + idx);
        }
    }

    const int mbase = (wid & 3) * 32;
    const int nbase = (wid >> 2) * 64;
    const int grp = lane >> 3, r8 = lane & 7;
    const int a_row = mbase + r8 + ((grp & 1) << 3);
    const int a_kof = (grp & 2) ? 8 : 0;
    const uint32_t aHi = smb + (uint32_t)(a_row * LDA + a_kof) * 2;
    const uint32_t aLo = aHi + A_LO_OFF;
    const int b_n  = r8 + ((grp & 2) << 2);
    const int b_kof = (grp & 1) ? 8 : 0;
    const uint32_t bBase = smb + GB_OFF + (uint32_t)((nbase + b_n) * 72 + b_kof) * 2;
    const int qr = lane >> 2, qc = (lane & 3) * 2;

    for (int nt = 0; nt < 6; ++nt) {
        float d[2][8][4];
#pragma unroll
        for (int mf = 0; mf < 2; ++mf)
#pragma unroll
            for (int nf = 0; nf < 8; ++nf)
#pragma unroll
                for (int q = 0; q < 4; ++q) d[mf][nf][q] = 0.f;

#pragma unroll
        for (int i = 0; i < 8; ++i) {
            int g = tid + i * 256;
            int half = g >> 10, j = g & 1023;
            int n = j >> 3, kq = j & 7;
            const __nv_bfloat16* W = half ? wl : wh;
            uint4 v = *(const uint4*)(W + (size_t)(nt * 128 + n) * 256 + kq * 8);
            *(uint4*)(sb + GB_OFF + half * B_HALF + n * LDB_B + kq * 16) = v;
        }
        __syncthreads();

        for (int c = 0; c < 4; ++c) {
            uint4 stg[8];
            if (c < 3) {
#pragma unroll
                for (int i = 0; i < 8; ++i) {
                    int g = tid + i * 256;
                    int half = g >> 10, j = g & 1023;
                    int n = j >> 3, kq = j & 7;
                    const __nv_bfloat16* W = half ? wl : wh;
                    stg[i] = *(const uint4*)(W + (size_t)(nt * 128 + n) * 256 + (c + 1) * 64 + kq * 8);
                }
            }
            const uint32_t bb0 = bBase + (uint32_t)(c & 1) * B_BUF;
#pragma unroll
            for (int kk8 = 0; kk8 < 4; ++kk8) {
                const int kg = c * 64 + kk8 * 16;
                uint32_t ah[2][4], al[2][4];
                ldsm4(ah[0], aHi + (uint32_t)kg * 2);
                ldsm4(ah[1], aHi + 16u * (LDA * 2) + (uint32_t)kg * 2);
                ldsm4(al[0], aLo + (uint32_t)kg * 2);
                ldsm4(al[1], aLo + 16u * (LDA * 2) + (uint32_t)kg * 2);
                uint32_t bh[4][4], bl[4][4];
                const uint32_t bb = bb0 + (uint32_t)kk8 * 32;
#pragma unroll
                for (int np = 0; np < 4; ++np) {
                    ldsm4(bh[np], bb + (uint32_t)np * (16 * LDB_B));
                    ldsm4(bl[np], bb + B_HALF + (uint32_t)np * (16 * LDB_B));
                }
#pragma unroll
                for (int mf = 0; mf < 2; ++mf)
#pragma unroll
                    for (int nf = 0; nf < 8; ++nf) {
                        const int np = nf >> 1, hv = (nf & 1) * 2;
                        mma16816(d[mf][nf], ah[mf], bh[np][hv], bh[np][hv + 1]);
                        mma16816(d[mf][nf], ah[mf], bl[np][hv], bl[np][hv + 1]);
                        mma16816(d[mf][nf], al[mf], bh[np][hv], bh[np][hv + 1]);
                    }
            }
            if (c < 3) {
#pragma unroll
                for (int i = 0; i < 8; ++i) {
                    int g = tid + i * 256;
                    int half = g >> 10, j = g & 1023;
                    int n = j >> 3, kq = j & 7;
                    *(uint4*)(sb + GB_OFF + ((c + 1) & 1) * B_BUF + half * B_HALF + n * LDB_B + kq * 16) = stg[i];
                }
            }
            __syncthreads();
        }

        // ---- epilogue: bias + split-bf16 store ----
#pragma unroll
        for (int mf = 0; mf < 2; ++mf)
#pragma unroll
            for (int h8 = 0; h8 < 2; ++h8) {
                int row = mbase + mf * 16 + h8 * 8 + qr;
                size_t base = (size_t)(blk * 128 + row) * 768 + nt * 128;
#pragma unroll
                for (int nf = 0; nf < 8; ++nf) {
                    int col = nbase + nf * 8 + qc;
                    float v0 = d[mf][nf][h8 * 2]     + bias[nt * 128 + col];
                    float v1 = d[mf][nf][h8 * 2 + 1] + bias[nt * 128 + col + 1];
                    float h0 = bf16rt(v0), h1 = bf16rt(v1);
                    *(uint32_t*)(qh_out + base + col) = pk(h0, h1);
                    *(uint32_t*)(ql_out + base + col) = pk(v0 - h0, v1 - h1);
                }
            }
    }
}

// ======================= fused attention + O-proj kernel =======================
// One CTA = one window (64 tokens). Attention: 8 warps = 8 heads, no barriers.
// Then O-proj GEMM in-CTA: A = attn-out (smem split), B = W_o^T streamed.
#define LDQ  264
#define AQH  0
#define AQL  33792
#define AKH  67584
#define AKL  101376
#define AVH  135168
#define AVL  168960
#define OB   67584            // O-proj B staging (overwrites K/V areas)
#define OB_HALF 36864         // 256 n * 144 B
#define AT_SMEM 202752

__global__ __launch_bounds__(256, 1)
void attn_fused(const __nv_bfloat16* __restrict__ qkvh, const __nv_bfloat16* __restrict__ qkvl,
                const __nv_bfloat16* __restrict__ woh, const __nv_bfloat16* __restrict__ wol,
                const float* __restrict__ bo,
                __nv_bfloat16* __restrict__ yh_out, __nv_bfloat16* __restrict__ yl_out,
                float* __restrict__ f32_out, int shifted)
{
    extern __shared__ char sb[];
    const uint32_t smb = smem_u32(sb);
    const int tid = threadIdx.x, wid = tid >> 5, lane = tid & 31;
    const int win = blockIdx.x;
    const int wh_ = (win & 63) >> 3, ww_ = win & 7;
    const int sh = shifted ? 4 : 0;

    // ---- load pre-split qkv: straight uint4 copies ----
    {
        const int t = tid >> 2;
        const size_t rbase = (size_t)(win * 64 + t) * 768;
#pragma unroll
        for (int i = 0; i < 24; ++i) {
            int col0 = ((tid & 3) + i * 4) * 8;      // 0..760
            int sel = col0 >> 8, c = col0 & 255;
            uint32_t bh = (sel == 0) ? AQH : (sel == 1) ? AKH : AVH;
            uint32_t off = (uint32_t)(t * LDQ + c) * 2;
            *(uint4*)(sb + bh + off)         = *(const uint4*)(qkvh + rbase + col0);
            *(uint4*)(sb + bh + 33792 + off) = *(const uint4*)(qkvl + rbase + col0);
        }
    }
    __syncthreads();

    const int head = wid;
    const int hcol = head * 32;
    const int arow = lane & 15, acolh = (lane >> 4) * 8;
    const int grp = lane >> 3, r8 = lane & 7;
    const int b_n = r8 + ((grp & 2) << 2), b_k = (grp & 1) * 8;
    const int v_k = r8 + ((grp & 1) << 3), v_n = (grp & 2) << 2;
    const int qr = lane >> 2, qc = (lane & 3) * 2;
    const float scale = 0.17677669529663687f;

    int creg[16];
#pragma unroll
    for (int j = 0; j < 8; ++j) {
        creg[2 * j]     = regid(wh_, ww_, j * 8 + qc);
        creg[2 * j + 1] = regid(wh_, ww_, j * 8 + qc + 1);
    }

    for (int mh = 0; mh < 2; ++mh) {
        const int rbase = mh * 32;
        uint32_t qh[2][2][4], ql[2][2][4];
#pragma unroll
        for (int i = 0; i < 2; ++i)
#pragma unroll
            for (int kt = 0; kt < 2; ++kt) {
                uint32_t off = (uint32_t)((rbase + i * 16 + arow) * LDQ + hcol + kt * 16 + acolh) * 2;
                ldsm4(qh[i][kt], smb + AQH + off);
                ldsm4(ql[i][kt], smb + AQL + off);
            }

        float s[2][8][4];
#pragma unroll
        for (int i = 0; i < 2; ++i)
#pragma unroll
            for (int j = 0; j < 8; ++j)
#pragma unroll
                for (int q = 0; q < 4; ++q) s[i][j][q] = 0.f;
#pragma unroll
        for (int kt = 0; kt < 2; ++kt)
#pragma unroll
            for (int ng = 0; ng < 4; ++ng) {
                uint32_t kh4[4], kl4[4];
                uint32_t ka = (uint32_t)((ng * 16 + b_n) * LDQ + hcol + kt * 16 + b_k) * 2;
                ldsm4(kh4, smb + AKH + ka);
                ldsm4(kl4, smb + AKL + ka);
#pragma unroll
                for (int i = 0; i < 2; ++i) {
                    mma16816(s[i][2 * ng],     qh[i][kt], kh4[0], kh4[1]);
                    mma16816(s[i][2 * ng],     qh[i][kt], kl4[0], kl4[1]);
                    mma16816(s[i][2 * ng],     ql[i][kt], kh4[0], kh4[1]);
                    mma16816(s[i][2 * ng + 1], qh[i][kt], kh4[2], kh4[3]);
                    mma16816(s[i][2 * ng + 1], qh[i][kt], kl4[2], kl4[3]);
                    mma16816(s[i][2 * ng + 1], ql[i][kt], kh4[2], kh4[3]);
                }
            }

        // scale + mask + softmax
#pragma unroll
        for (int i = 0; i < 2; ++i) {
            int rr0 = regid(wh_, ww_, rbase + i * 16 + qr);
            int rr1 = regid(wh_, ww_, rbase + i * 16 + qr + 8);
#pragma unroll
            for (int j = 0; j < 8; ++j) {
                s[i][j][0] *= scale; s[i][j][1] *= scale;
                s[i][j][2] *= scale; s[i][j][3] *= scale;
                if (shifted) {
                    if (creg[2 * j]     != rr0) s[i][j][0] += -1e9f;
                    if (creg[2 * j + 1] != rr0) s[i][j][1] += -1e9f;
                    if (creg[2 * j]     != rr1) s[i][j][2] += -1e9f;
                    if (creg[2 * j + 1] != rr1) s[i][j][3] += -1e9f;
                }
            }
            float m0 = -3.4e38f, m1 = -3.4e38f;
#pragma unroll
            for (int j = 0; j < 8; ++j) {
                m0 = fmaxf(m0, fmaxf(s[i][j][0], s[i][j][1]));
                m1 = fmaxf(m1, fmaxf(s[i][j][2], s[i][j][3]));
            }
            m0 = fmaxf(m0, __shfl_xor_sync(0xffffffffu, m0, 1));
            m0 = fmaxf(m0, __shfl_xor_sync(0xffffffffu, m0, 2));
            m1 = fmaxf(m1, __shfl_xor_sync(0xffffffffu, m1, 1));
            m1 = fmaxf(m1, __shfl_xor_sync(0xffffffffu, m1, 2));
            float s0 = 0.f, s1 = 0.f;
#pragma unroll
            for (int j = 0; j < 8; ++j) {
                s[i][j][0] = __expf(s[i][j][0] - m0); s0 += s[i][j][0];
                s[i][j][1] = __expf(s[i][j][1] - m0); s0 += s[i][j][1];
                s[i][j][2] = __expf(s[i][j][2] - m1); s1 += s[i][j][2];
                s[i][j][3] = __expf(s[i][j][3] - m1); s1 += s[i][j][3];
            }
            s0 += __shfl_xor_sync(0xffffffffu, s0, 1);
            s0 += __shfl_xor_sync(0xffffffffu, s0, 2);
            s1 += __shfl_xor_sync(0xffffffffu, s1, 1);
            s1 += __shfl_xor_sync(0xffffffffu, s1, 2);
            float i0 = 1.f / s0, i1 = 1.f / s1;
#pragma unroll
            for (int j = 0; j < 8; ++j) {
                s[i][j][0] *= i0; s[i][j][1] *= i0;
                s[i][j][2] *= i1; s[i][j][3] *= i1;
            }
        }

        // pack P to A-fragments (hi/lo)
        uint32_t ph[2][4][4], pl[2][4][4];
#pragma unroll
        for (int i = 0; i < 2; ++i)
#pragma unroll
            for (int kt = 0; kt < 4; ++kt) {
                const float* e = s[i][2 * kt];
                const float* o2 = s[i][2 * kt + 1];
                float h, h2;
                h = bf16rt(e[0]);  h2 = bf16rt(e[1]);
                ph[i][kt][0] = pk(h, h2);  pl[i][kt][0] = pk(e[0] - h, e[1] - h2);
                h = bf16rt(e[2]);  h2 = bf16rt(e[3]);
                ph[i][kt][1] = pk(h, h2);  pl[i][kt][1] = pk(e[2] - h, e[3] - h2);
                h = bf16rt(o2[0]); h2 = bf16rt(o2[1]);
                ph[i][kt][2] = pk(h, h2);  pl[i][kt][2] = pk(o2[0] - h, o2[1] - h2);
                h = bf16rt(o2[2]); h2 = bf16rt(o2[3]);
                ph[i][kt][3] = pk(h, h2);  pl[i][kt][3] = pk(o2[2] - h, o2[3] - h2);
            }

        // O = P V
        float o[2][4][4];
#pragma unroll
        for (int i = 0; i < 2; ++i)
#pragma unroll
            for (int nt = 0; nt < 4; ++nt)
#pragma unroll
                for (int q = 0; q < 4; ++q) o[i][nt][q] = 0.f;
#pragma unroll
        for (int kt = 0; kt < 4; ++kt)
#pragma unroll
            for (int ng = 0; ng < 2; ++ng) {
                uint32_t vh4[4], vl4[4];
                uint32_t va = (uint32_t)((kt * 16 + v_k) * LDQ + hcol + ng * 16 + v_n) * 2;
                ldsm4t(vh4, smb + AVH + va);
                ldsm4t(vl4, smb + AVL + va);
#pragma unroll
                for (int i = 0; i < 2; ++i) {
                    mma16816(o[i][2 * ng],     ph[i][kt], vh4[0], vh4[1]);
                    mma16816(o[i][2 * ng],     ph[i][kt], vl4[0], vl4[1]);
                    mma16816(o[i][2 * ng],     pl[i][kt], vh4[0], vh4[1]);
                    mma16816(o[i][2 * ng + 1], ph[i][kt], vh4[2], vh4[3]);
                    mma16816(o[i][2 * ng + 1], ph[i][kt], vl4[2], vl4[3]);
                    mma16816(o[i][2 * ng + 1], pl[i][kt], vh4[2], vh4[3]);
                }
            }

        // ---- store attn-out (split bf16) into dead Q smem: own cols, own rows ----
#pragma unroll
        for (int i = 0; i < 2; ++i) {
#pragma unroll
            for (int nt = 0; nt < 4; ++nt) {
                int col = hcol + nt * 8 + qc;
                int r0 = rbase + i * 16 + qr;
                float v0 = o[i][nt][0], v1 = o[i][nt][1];
                float h0 = bf16rt(v0), h1 = bf16rt(v1);
                uint32_t off0 = (uint32_t)(r0 * LDQ + col) * 2;
                *(uint32_t*)(sb + AQH + off0) = pk(h0, h1);
                *(uint32_t*)(sb + AQL + off0) = pk(v0 - h0, v1 - h1);
                float v2 = o[i][nt][2], v3 = o[i][nt][3];
                float h2 = bf16rt(v2), h3 = bf16rt(v3);
                uint32_t off1 = (uint32_t)((r0 + 8) * LDQ + col) * 2;
                *(uint32_t*)(sb + AQH + off1) = pk(h2, h3);
                *(uint32_t*)(sb + AQL + off1) = pk(v2 - h2, v3 - h3);
            }
        }
    }
    __syncthreads();   // attn-out complete; K/V smem dead

    // ======= O-projection: [64,256] = A @ W_o^T, A in smem (AQH/AQL) =======
    const int mbase = (wid & 1) * 32;
    const int nbase = (wid >> 1) * 64;
    const uint32_t aHi = smb + AQH + (uint32_t)((mbase + r8 + ((grp & 1) << 3)) * LDQ + ((grp & 2) ? 8 : 0)) * 2;
    const uint32_t aLo = aHi + (AQL - AQH);
    const uint32_t bBase = smb + OB + (uint32_t)((nbase + b_n) * 72 + b_k) * 2;

    float d[2][8][4];
#pragma unroll
    for (int mf = 0; mf < 2; ++mf)
#pragma unroll
        for (int nf = 0; nf < 8; ++nf)
#pragma unroll
            for (int q = 0; q < 4; ++q) d[mf][nf][q] = 0.f;

    for (int c = 0; c < 4; ++c) {
        // stage B chunk [256 n][64 k] hi+lo
#pragma unroll
        for (int i = 0; i < 16; ++i) {
            int g = tid + i * 256;
            int half = g >> 11, j = g & 2047;
            int n = j >> 3, kq = j & 7;
            const __nv_bfloat16* W = half ? wol : woh;
            uint4 v = *(const uint4*)(W + (size_t)n * 256 + c * 64 + kq * 8);
            *(uint4*)(sb + OB + half * OB_HALF + n * LDB_B + kq * 16) = v;
        }
        __syncthreads();
#pragma unroll
        for (int kk8 = 0; kk8 < 4; ++kk8) {
            const int kg = c * 64 + kk8 * 16;
            uint32_t ah[2][4], al[2][4];
            ldsm4(ah[0], aHi + (uint32_t)kg * 2);
            ldsm4(ah[1], aHi + 16u * (LDQ * 2) + (uint32_t)kg * 2);
            ldsm4(al[0], aLo + (uint32_t)kg * 2);
            ldsm4(al[1], aLo + 16u * (LDQ * 2) + (uint32_t)kg * 2);
            uint32_t bh4[4][4], bl4[4][4];
            const uint32_t bb = bBase + (uint32_t)kk8 * 32;
#pragma unroll
            for (int np = 0; np < 4; ++np) {
                ldsm4(bh4[np], bb + (uint32_t)np * (16 * LDB_B));
                ldsm4(bl4[np], bb + OB_HALF + (uint32_t)np * (16 * LDB_B));
            }
#pragma unroll
            for (int mf = 0; mf < 2; ++mf)
#pragma unroll
                for (int nf = 0; nf < 8; ++nf) {
                    const int np = nf >> 1, hv = (nf & 1) * 2;
                    mma16816(d[mf][nf], ah[mf], bh4[np][hv], bh4[np][hv + 1]);
                    mma16816(d[mf][nf], ah[mf], bl4[np][hv], bl4[np][hv + 1]);
                    mma16816(d[mf][nf], al[mf], bh4[np][hv], bh4[np][hv + 1]);
                }
        }
        if (c < 3) __syncthreads();
    }

    // ---- epilogue: bias + image scatter (+roll back) ----
#pragma unroll
    for (int mf = 0; mf < 2; ++mf)
#pragma unroll
        for (int h8 = 0; h8 < 2; ++h8) {
            int row = mbase + mf * 16 + h8 * 8 + qr;
            int tok = win * 64 + row;
            int m = tok >> 12, w = (tok >> 6) & 63, tt = tok & 63;
            int gh = ((w >> 3) * 8 + (tt >> 3) + sh) & 63;
            int gw = ((w & 7) * 8 + (tt & 7) + sh) & 63;
            size_t base = (size_t)((m * 64 + gh) * 64 + gw) * 256;
#pragma unroll
            for (int nf = 0; nf < 8; ++nf) {
                int col = nbase + nf * 8 + qc;
                float v0 = d[mf][nf][h8 * 2]     + bo[col];
                float v1 = d[mf][nf][h8 * 2 + 1] + bo[col + 1];
                if (!shifted) {
                    float h0 = bf16rt(v0), h1 = bf16rt(v1);
                    *(uint32_t*)(yh_out + base + col) = pk(h0, h1);
                    *(uint32_t*)(yl_out + base + col) = pk(v0 - h0, v1 - h1);
                } else {
                    *(float2*)(f32_out + base + col) = make_float2(v0, v1);
                }
            }
        }
}

// ======================= launch =======================
extern "C" void kernel_launch(void* const* d_in, const int* in_sizes, int n_in,
                              void* d_out, int out_size) {
    (void)in_sizes; (void)n_in; (void)out_size;
    const float* x    = (const float*)d_in[0];
    const float* wqkv = (const float*)d_in[1];
    const float* bqkv = (const float*)d_in[2];
    const float* wo   = (const float*)d_in[3];
    const float* bo   = (const float*)d_in[4];
    float* out = (float*)d_out;

    cudaFuncSetAttribute(gemm_qkv,   cudaFuncAttributeMaxDynamicSharedMemorySize, GS_SMEM);
    cudaFuncSetAttribute(attn_fused, cudaFuncAttributeMaxDynamicSharedMemorySize, AT_SMEM);

    __nv_bfloat16 *wqh, *wql, *woh, *wol, *qh, *ql, *yh, *yl;
    cudaGetSymbolAddress((void**)&wqh, g_wtq_hi);
    cudaGetSymbolAddress((void**)&wql, g_wtq_lo);
    cudaGetSymbolAddress((void**)&woh, g_wto_hi);
    cudaGetSymbolAddress((void**)&wol, g_wto_lo);
    cudaGetSymbolAddress((void**)&qh,  g_qkvh);
    cudaGetSymbolAddress((void**)&ql,  g_qkvl);
    cudaGetSymbolAddress((void**)&yh,  g_yh);
    cudaGetSymbolAddress((void**)&yl,  g_yl);

    prep_kernel<<<1024, 256>>>(wqkv, wo);

    for (int pass = 0; pass < 2; ++pass) {
        gemm_qkv<<<1024, 256, GS_SMEM>>>(x, yh, yl, wqh, wql, bqkv, qh, ql, pass);
        attn_fused<<<2048, 256, AT_SMEM>>>(qh, ql, woh, wol, bo, yh, yl, out, pass);
    }
}